// round 11
// baseline (speedup 1.0000x reference)
#include <cuda_runtime.h>
#include <math.h>

#define M_PTS    2048
#define N_VOX    65536
#define NPGRID   10                      // point grid: 10^3 cells, pitch 0.5 (q-space), [-2.5,2.5)
#define NPCELL   1000
#define NVB      9                       // voxel base-cell grid 9^3
#define NVCELL   729
#define VHB      16                      // histogram/scatter blocks (blockIdx 1..16)
#define TPB      128

__device__ float4 g_sorted[M_PTS];           // points grouped by point-cell (q-space)
__device__ int    g_pcellstart[NPCELL + 1];
__device__ int    g_vcount[NVCELL];          // zero at load; re-zeroed each run by last block
__device__ int    g_vstart[NVCELL + 1];
__device__ int    g_vcur[NVCELL];
__device__ float4 g_vpack[N_VOX];            // voxels sorted by base cell: {ux,uy,uz, bits(idx)}
__device__ float4 g_part[NVCELL];
__device__ unsigned g_chist;                 // all zero-init; reset by last block each run
__device__ unsigned g_fscan;
__device__ unsigned g_cscat;
__device__ unsigned g_cdone;

struct BuildS {
    float px[M_PTS], py[M_PTS], pz[M_PTS];
    short cellof[M_PTS];
    int   cnt[NPCELL];
    int   cur[NPCELL];
    float Ms[16];
    int   wa[4], wb[4];
};
struct HistS  { int h[NVCELL]; };
struct QueryS { float4 stage[M_PTS]; float red[4][4]; unsigned amLast; };
union SmemU { BuildS b; HistS h; QueryS q; };

__device__ __forceinline__ int vox_base_cell(float cx, float cy, float cz) {
    // u = 2c (q-space); base index floor(2u + 4.5) = floor(4c + 4.5) in [0,8]
    int ix = (int)floorf(4.0f * cx + 4.5f);
    int iy = (int)floorf(4.0f * cy + 4.5f);
    int iz = (int)floorf(4.0f * cz + 4.5f);
    return (ix * NVB + iy) * NVB + iz;
}

__device__ __forceinline__ void spin_until(unsigned* ctr, unsigned target) {
    while (atomicAdd(ctr, 0u) < target) __nanosleep(64);
}

__global__ void __launch_bounds__(TPB) mega_kernel(
    const float* __restrict__ quat,    const float* __restrict__ tran,
    const float* __restrict__ model,   const float* __restrict__ view,
    const float* __restrict__ centers, const float* __restrict__ freev,
    const float* __restrict__ occo,    const float* __restrict__ masks,
    float* __restrict__ out) {
    __shared__ SmemU sm;
    const int t = threadIdx.x;
    const int lane = t & 31, w = t >> 5;
    const int B = blockIdx.x;

    if (B == 0) {
        // ================= builder block: matrix + point grid + scans =================
        for (int i = t; i < NPCELL; i += TPB) sm.b.cnt[i] = 0;
        if (t == 0) {
            float q[4]; float s = 0.0f;
#pragma unroll
            for (int i = 0; i < 4; i++) { q[i] = quat[i]; s += q[i] * q[i]; }
            float f = sqrtf(2.0f / s);
#pragma unroll
            for (int i = 0; i < 4; i++) q[i] *= f;
            float Q[4][4];
#pragma unroll
            for (int i = 0; i < 4; i++)
#pragma unroll
                for (int j = 0; j < 4; j++) Q[i][j] = q[i] * q[j];
            float E[4][4] = {
                {1.0f - Q[2][2] - Q[3][3], Q[1][2] - Q[3][0],        Q[1][3] + Q[2][0],        tran[0]},
                {Q[1][2] + Q[3][0],        1.0f - Q[1][1] - Q[3][3], Q[2][3] - Q[1][0],        tran[1]},
                {Q[1][3] - Q[2][0],        Q[2][3] + Q[1][0],        1.0f - Q[1][1] - Q[2][2], tran[2]},
                {0.0f, 0.0f, 0.0f, 1.0f}};
            float A[4][8];
            for (int i = 0; i < 4; i++)
                for (int j = 0; j < 4; j++) {
                    A[i][j]     = view[i * 4 + j];
                    A[i][j + 4] = (i == j) ? 1.0f : 0.0f;
                }
            for (int col = 0; col < 4; col++) {
                int piv = col; float best = fabsf(A[col][col]);
                for (int r = col + 1; r < 4; r++)
                    if (fabsf(A[r][col]) > best) { best = fabsf(A[r][col]); piv = r; }
                if (piv != col)
                    for (int j = 0; j < 8; j++) { float tmp = A[col][j]; A[col][j] = A[piv][j]; A[piv][j] = tmp; }
                float d = 1.0f / A[col][col];
                for (int j = 0; j < 8; j++) A[col][j] *= d;
                for (int r = 0; r < 4; r++) {
                    if (r == col) continue;
                    float m = A[r][col];
                    for (int j = 0; j < 8; j++) A[r][j] -= m * A[col][j];
                }
            }
            for (int i = 0; i < 4; i++)
                for (int j = 0; j < 4; j++) {
                    float acc = 0.0f;
                    for (int k = 0; k < 4; k++) acc += A[i][k + 4] * E[k][j];
                    sm.b.Ms[i * 4 + j] = acc;
                }
        }
        __syncthreads();

        // transform + bin points
        for (int i = t; i < M_PTS; i += TPB) {
            float mx = model[3 * i + 0], my = model[3 * i + 1], mz = model[3 * i + 2];
            const float* Ms = sm.b.Ms;
            float hx = Ms[0]  * mx + Ms[1]  * my + Ms[2]  * mz + Ms[3];
            float hy = Ms[4]  * mx + Ms[5]  * my + Ms[6]  * mz + Ms[7];
            float hz = Ms[8]  * mx + Ms[9]  * my + Ms[10] * mz + Ms[11];
            float hw = Ms[12] * mx + Ms[13] * my + Ms[14] * mz + Ms[15];
            float inv = 2.0f / hw;               // pred / RES
            float x = hx * inv, y = hy * inv, z = hz * inv;
            sm.b.px[i] = x; sm.b.py[i] = y; sm.b.pz[i] = z;
            int ix = (int)floorf(2.0f * x + 5.0f);
            int iy = (int)floorf(2.0f * y + 5.0f);
            int iz = (int)floorf(2.0f * z + 5.0f);
            short cell = -1;
            // points outside [-2.5,2.5)^3 are > 0.25 from every center -> clamp kills them
            if (ix >= 0 && ix < NPGRID && iy >= 0 && iy < NPGRID && iz >= 0 && iz < NPGRID) {
                cell = (short)((ix * NPGRID + iy) * NPGRID + iz);
                atomicAdd(&sm.b.cnt[cell], 1);
            }
            sm.b.cellof[i] = cell;
        }
        __syncthreads();

        // exclusive scan over NPCELL (8 cells/thread)
        {
            int bidx = t * 8;
            int s8[8]; int tot = 0;
#pragma unroll
            for (int j = 0; j < 8; j++) {
                int idx = bidx + j;
                int c = (idx < NPCELL) ? sm.b.cnt[idx] : 0;
                s8[j] = tot; tot += c;
            }
            int incl = tot;
#pragma unroll
            for (int off = 1; off < 32; off <<= 1) {
                int v = __shfl_up_sync(0xffffffffu, incl, off);
                if (lane >= off) incl += v;
            }
            if (lane == 31) sm.b.wa[w] = incl;
            __syncthreads();
            if (t == 0) { int a = 0; for (int i = 0; i < 4; i++) { sm.b.wb[i] = a; a += sm.b.wa[i]; } }
            __syncthreads();
            int excl = sm.b.wb[w] + incl - tot;
#pragma unroll
            for (int j = 0; j < 8; j++) {
                int idx = bidx + j;
                if (idx < NPCELL) { int v = excl + s8[j]; g_pcellstart[idx] = v; sm.b.cur[idx] = v; }
            }
            if (t == TPB - 1) g_pcellstart[NPCELL] = excl + tot;
        }
        __syncthreads();

        // scatter points into cell-grouped order
        for (int i = t; i < M_PTS; i += TPB) {
            int cell = sm.b.cellof[i];
            if (cell >= 0) {
                int pos = atomicAdd(&sm.b.cur[cell], 1);
                g_sorted[pos] = make_float4(sm.b.px[i], sm.b.py[i], sm.b.pz[i], 0.0f);
            }
        }
        __threadfence();
        __syncthreads();
        if (t == 0) spin_until(&g_chist, VHB);
        __syncthreads();
        __threadfence();

        // exclusive scan over NVCELL voxel counts (6 cells/thread)
        {
            int bidx = t * 6;
            int s6[6]; int tot = 0;
#pragma unroll
            for (int j = 0; j < 6; j++) {
                int idx = bidx + j;
                int c = (idx < NVCELL) ? g_vcount[idx] : 0;
                s6[j] = tot; tot += c;
            }
            int incl = tot;
#pragma unroll
            for (int off = 1; off < 32; off <<= 1) {
                int v = __shfl_up_sync(0xffffffffu, incl, off);
                if (lane >= off) incl += v;
            }
            if (lane == 31) sm.b.wa[w] = incl;
            __syncthreads();
            if (t == 0) { int a = 0; for (int i = 0; i < 4; i++) { sm.b.wb[i] = a; a += sm.b.wa[i]; } }
            __syncthreads();
            int excl = sm.b.wb[w] + incl - tot;
#pragma unroll
            for (int j = 0; j < 6; j++) {
                int idx = bidx + j;
                if (idx < NVCELL) { int v = excl + s6[j]; g_vstart[idx] = v; g_vcur[idx] = v; }
            }
            if (t == TPB - 1) g_vstart[NVCELL] = excl + tot;
        }
        __threadfence();
        __syncthreads();
        if (t == 0) atomicExch(&g_fscan, 1u);
    } else if (B <= VHB) {
        // ================= histogram + scatter blocks =================
        for (int i = t; i < NVCELL; i += TPB) sm.h.h[i] = 0;
        __syncthreads();
        const int base = (B - 1) * (N_VOX / VHB);
        for (int k = 0; k < N_VOX / VHB / TPB; k++) {
            int v = base + k * TPB + t;
            float cx = centers[3 * v + 0], cy = centers[3 * v + 1], cz = centers[3 * v + 2];
            atomicAdd(&sm.h.h[vox_base_cell(cx, cy, cz)], 1);
        }
        __syncthreads();
        for (int i = t; i < NVCELL; i += TPB) {
            int c = sm.h.h[i];
            if (c) atomicAdd(&g_vcount[i], c);
        }
        __threadfence();
        __syncthreads();
        if (t == 0) {
            atomicAdd(&g_chist, 1u);
            spin_until(&g_fscan, 1u);
        }
        __syncthreads();
        __threadfence();
        // scatter voxels (centers L2-hot from first pass)
        for (int k = 0; k < N_VOX / VHB / TPB; k++) {
            int v = base + k * TPB + t;
            float cx = centers[3 * v + 0], cy = centers[3 * v + 1], cz = centers[3 * v + 2];
            int pos = atomicAdd(&g_vcur[vox_base_cell(cx, cy, cz)], 1);
            g_vpack[pos] = make_float4(2.0f * cx, 2.0f * cy, 2.0f * cz, __int_as_float(v));
        }
        __threadfence();
        __syncthreads();
        if (t == 0) atomicAdd(&g_cscat, 1u);
    }

    // ================= query phase (all 729 blocks, one voxel cell each) =================
    if (t == 0) spin_until(&g_cscat, VHB);
    __syncthreads();
    __threadfence();

    const int ix0 = B / (NVB * NVB);
    const int rem = B % (NVB * NVB);
    const int iy0 = rem / NVB;
    const int iz0 = rem % NVB;

    // 4 contiguous point runs (z-cells iz0, iz0+1 adjacent in point grid)
    int rs[4], re[4], off[4];
    int nloc = 0;
#pragma unroll
    for (int a = 0; a < 2; a++)
#pragma unroll
        for (int b = 0; b < 2; b++) {
            int r = a * 2 + b;
            int cb = ((ix0 + a) * NPGRID + (iy0 + b)) * NPGRID + iz0;
            rs[r] = g_pcellstart[cb];
            re[r] = g_pcellstart[cb + 2];
            off[r] = nloc;
            nloc += re[r] - rs[r];
        }

    // stage neighborhood points into shared memory (coalesced)
#pragma unroll
    for (int r = 0; r < 4; r++) {
        int l = re[r] - rs[r];
        for (int k = t; k < l; k += TPB) sm.q.stage[off[r] + k] = g_sorted[rs[r] + k];
    }
    __syncthreads();

    const int vs = g_vstart[B], ve = g_vstart[B + 1];
    float aps = 0.f, as1 = 0.f, as2 = 0.f, ams = 0.f;

    for (int basei = vs; basei < ve; basei += TPB) {
        int i = basei + t;
        bool act = (i < ve);
        float4 vp = act ? g_vpack[i] : make_float4(0.f, 0.f, 0.f, 0.f);
        float ux = vp.x, uy = vp.y, uz = vp.z;

        float m0 = 1e30f, m1 = 1e30f, m2 = 1e30f, m3 = 1e30f;
        int k = 0;
        for (; k + 4 <= nloc; k += 4) {          // unroll-4, 4 independent chains
            float4 p0 = sm.q.stage[k + 0];
            float4 p1 = sm.q.stage[k + 1];
            float4 p2 = sm.q.stage[k + 2];
            float4 p3 = sm.q.stage[k + 3];
            float dx0 = ux - p0.x, dy0 = uy - p0.y, dz0 = uz - p0.z;
            float dx1 = ux - p1.x, dy1 = uy - p1.y, dz1 = uz - p1.z;
            float dx2 = ux - p2.x, dy2 = uy - p2.y, dz2 = uz - p2.z;
            float dx3 = ux - p3.x, dy3 = uy - p3.y, dz3 = uz - p3.z;
            m0 = fminf(m0, fmaf(dx0, dx0, fmaf(dy0, dy0, dz0 * dz0)));
            m1 = fminf(m1, fmaf(dx1, dx1, fmaf(dy1, dy1, dz1 * dz1)));
            m2 = fminf(m2, fmaf(dx2, dx2, fmaf(dy2, dy2, dz2 * dz2)));
            m3 = fminf(m3, fmaf(dx3, dx3, fmaf(dy3, dy3, dz3 * dz3)));
        }
        for (; k < nloc; k++) {
            float4 p = sm.q.stage[k];
            float dx = ux - p.x, dy = uy - p.y, dz = uz - p.z;
            m0 = fminf(m0, fmaf(dx, dx, fmaf(dy, dy, dz * dz)));
        }
        float m = fminf(fminf(m0, m1), fminf(m2, m3));

        float fo = 0.f, mk = 0.f;
        if (act) {
            int v = __float_as_int(vp.w);
            fo = freev[v] + occo[v];
            mk = masks[v];
        }
        float d = sqrtf(fmaxf(m, 0.0f));
        d = fminf(d, 0.25f);
        float o = fmaxf(1.0f - 4.0f * d, 0.0f);
        if (!act) o = 0.f;
        aps += o; as1 += fo * o; as2 += mk * o; ams += mk;
    }

    const unsigned full = 0xffffffffu;
#pragma unroll
    for (int offs = 16; offs > 0; offs >>= 1) {
        aps += __shfl_down_sync(full, aps, offs);
        as1 += __shfl_down_sync(full, as1, offs);
        as2 += __shfl_down_sync(full, as2, offs);
        ams += __shfl_down_sync(full, ams, offs);
    }
    if (lane == 0) { sm.q.red[0][w] = aps; sm.q.red[1][w] = as1; sm.q.red[2][w] = as2; sm.q.red[3][w] = ams; }
    __syncthreads();
    if (t == 0) {
        float tps = 0.f, ts1 = 0.f, ts2 = 0.f, tms = 0.f;
#pragma unroll
        for (int i = 0; i < 4; i++) {
            tps += sm.q.red[0][i]; ts1 += sm.q.red[1][i];
            ts2 += sm.q.red[2][i]; tms += sm.q.red[3][i];
        }
        g_part[B] = make_float4(tps, ts1, ts2, tms);
        __threadfence();
        unsigned r = atomicAdd(&g_cdone, 1u);
        sm.q.amLast = (r == NVCELL - 1) ? 1u : 0u;
    }
    __syncthreads();

    if (sm.q.amLast) {
        __threadfence();
        float4 acc = make_float4(0.f, 0.f, 0.f, 0.f);
        for (int i = t; i < NVCELL; i += TPB) {
            float4 p = __ldcg(&g_part[i]);
            acc.x += p.x; acc.y += p.y; acc.z += p.z; acc.w += p.w;
        }
#pragma unroll
        for (int offs = 16; offs > 0; offs >>= 1) {
            acc.x += __shfl_down_sync(full, acc.x, offs);
            acc.y += __shfl_down_sync(full, acc.y, offs);
            acc.z += __shfl_down_sync(full, acc.z, offs);
            acc.w += __shfl_down_sync(full, acc.w, offs);
        }
        if (lane == 0) { sm.q.red[0][w] = acc.x; sm.q.red[1][w] = acc.y; sm.q.red[2][w] = acc.z; sm.q.red[3][w] = acc.w; }
        __syncthreads();
        // reset all gates/counters for the next graph replay
        for (int i = t; i < NVCELL; i += TPB) g_vcount[i] = 0;
        if (t == 0) {
            double ps = 0.0, s1 = 0.0, s2 = 0.0, ms = 0.0;
#pragma unroll
            for (int i = 0; i < 4; i++) {
                ps += (double)sm.q.red[0][i]; s1 += (double)sm.q.red[1][i];
                s2 += (double)sm.q.red[2][i]; ms += (double)sm.q.red[3][i];
            }
            double t1 = (ps > 0.0) ? s1 / ps : 0.0;
            double t2 = (ms > 0.0) ? s2 / ms : 0.0;
            out[0] = (float)(t1 - t2);
            g_chist = 0; g_fscan = 0; g_cscat = 0; g_cdone = 0;
        }
    }
}

extern "C" void kernel_launch(void* const* d_in, const int* in_sizes, int n_in,
                              void* d_out, int out_size) {
    const float* quat    = (const float*)d_in[0];
    const float* tran    = (const float*)d_in[1];
    const float* model   = (const float*)d_in[2];
    const float* view    = (const float*)d_in[3];
    const float* centers = (const float*)d_in[4];
    const float* freev   = (const float*)d_in[5];
    const float* occo    = (const float*)d_in[6];
    const float* masks   = (const float*)d_in[7];
    (void)in_sizes; (void)n_in; (void)out_size;

    mega_kernel<<<NVCELL, TPB>>>(quat, tran, model, view, centers,
                                 freev, occo, masks, (float*)d_out);
}

// round 12
// speedup vs baseline: 2.4251x; 2.4251x over previous
#include <cuda_runtime.h>
#include <math.h>

#define M_PTS    2048
#define N_VOX    65536
#define TPB      256
#define GRID     (N_VOX / TPB)           // 256 blocks, 1 voxel per thread
#define PPT      (M_PTS / TPB)           // 8 points per thread
#define NPGRID   10                      // point grid: 10^3 cells, pitch 0.5 (q-space), [-2.5,2.5)
#define NPCELL   1000
#define NPPAD    1024

__device__ float4 g_part[GRID];          // per-block partials {pred_sum, s1, s2, mask_sum}
__device__ unsigned g_done = 0;          // zero-init; self-resetting each run

struct Smem {
    float4 pts[M_PTS];     // block-private cell-sorted points (32 KB)
    int    cnt[NPPAD];     // histogram (padded)
    int    cur[NPCELL];    // scatter cursors
    int    cstart[NPCELL + 1];
    float  Ms[16];
    float  red[4][TPB / 32];
    int    wa[TPB / 32];
    unsigned amLast;
};

__global__ void __launch_bounds__(TPB) icc_kernel(
    const float* __restrict__ quat,    const float* __restrict__ tran,
    const float* __restrict__ model,   const float* __restrict__ view,
    const float* __restrict__ centers, const float* __restrict__ freev,
    const float* __restrict__ occo,    const float* __restrict__ masks,
    float* __restrict__ out) {
    __shared__ Smem sm;
    const int t = threadIdx.x;
    const int lane = t & 31, w = t >> 5;

    // ---- issue the voxel-side loads early (independent of everything) ----
    const int v = blockIdx.x * TPB + t;
    const float cx = centers[3 * v + 0];
    const float cy = centers[3 * v + 1];
    const float cz = centers[3 * v + 2];
    const float fo = freev[v] + occo[v];
    const float mk = masks[v];

    for (int i = t; i < NPPAD; i += TPB) sm.cnt[i] = 0;

    // ---- every block computes mat_world = inv(view) @ quat_matrix (t0, fp32) ----
    if (t == 0) {
        float q[4]; float s = 0.0f;
#pragma unroll
        for (int i = 0; i < 4; i++) { q[i] = quat[i]; s += q[i] * q[i]; }
        float f = sqrtf(2.0f / s);
#pragma unroll
        for (int i = 0; i < 4; i++) q[i] *= f;
        float Q[4][4];
#pragma unroll
        for (int i = 0; i < 4; i++)
#pragma unroll
            for (int j = 0; j < 4; j++) Q[i][j] = q[i] * q[j];
        float E[4][4] = {
            {1.0f - Q[2][2] - Q[3][3], Q[1][2] - Q[3][0],        Q[1][3] + Q[2][0],        tran[0]},
            {Q[1][2] + Q[3][0],        1.0f - Q[1][1] - Q[3][3], Q[2][3] - Q[1][0],        tran[1]},
            {Q[1][3] - Q[2][0],        Q[2][3] + Q[1][0],        1.0f - Q[1][1] - Q[2][2], tran[2]},
            {0.0f, 0.0f, 0.0f, 1.0f}};
        float A[4][8];
        for (int i = 0; i < 4; i++)
            for (int j = 0; j < 4; j++) {
                A[i][j]     = view[i * 4 + j];
                A[i][j + 4] = (i == j) ? 1.0f : 0.0f;
            }
        for (int col = 0; col < 4; col++) {
            int piv = col; float best = fabsf(A[col][col]);
            for (int r = col + 1; r < 4; r++)
                if (fabsf(A[r][col]) > best) { best = fabsf(A[r][col]); piv = r; }
            if (piv != col)
                for (int j = 0; j < 8; j++) { float tmp = A[col][j]; A[col][j] = A[piv][j]; A[piv][j] = tmp; }
            float d = 1.0f / A[col][col];
            for (int j = 0; j < 8; j++) A[col][j] *= d;
            for (int r = 0; r < 4; r++) {
                if (r == col) continue;
                float m = A[r][col];
                for (int j = 0; j < 8; j++) A[r][j] -= m * A[col][j];
            }
        }
        for (int i = 0; i < 4; i++)
            for (int j = 0; j < 4; j++) {
                float acc = 0.0f;
                for (int k = 0; k < 4; k++) acc += A[i][k + 4] * E[k][j];
                sm.Ms[i * 4 + j] = acc;
            }
    }
    __syncthreads();

    // ---- transform 8 points/thread into registers; histogram ----
    float rx[PPT], ry[PPT], rz[PPT];
    int   rc[PPT];
#pragma unroll
    for (int k = 0; k < PPT; k++) {
        int i = k * TPB + t;                       // coalesced
        float mx = model[3 * i + 0], my = model[3 * i + 1], mz = model[3 * i + 2];
        const float* Ms = sm.Ms;
        float hx = Ms[0]  * mx + Ms[1]  * my + Ms[2]  * mz + Ms[3];
        float hy = Ms[4]  * mx + Ms[5]  * my + Ms[6]  * mz + Ms[7];
        float hz = Ms[8]  * mx + Ms[9]  * my + Ms[10] * mz + Ms[11];
        float hw = Ms[12] * mx + Ms[13] * my + Ms[14] * mz + Ms[15];
        float inv = 2.0f / hw;                      // pred / RES
        float x = hx * inv, y = hy * inv, z = hz * inv;
        rx[k] = x; ry[k] = y; rz[k] = z;
        int ix = (int)floorf(2.0f * x + 5.0f);
        int iy = (int)floorf(2.0f * y + 5.0f);
        int iz = (int)floorf(2.0f * z + 5.0f);
        int cell = -1;
        // points outside [-2.5,2.5)^3 are > 0.25 (L2) from every center in
        // [-2,2)^3 (q-space) -> the RES/2 clamp makes them irrelevant: discard.
        if (ix >= 0 && ix < NPGRID && iy >= 0 && iy < NPGRID && iz >= 0 && iz < NPGRID) {
            cell = (ix * NPGRID + iy) * NPGRID + iz;
            atomicAdd(&sm.cnt[cell], 1);
        }
        rc[k] = cell;
    }
    __syncthreads();

    // ---- exclusive scan over 1024 cells (4/thread) ----
    {
        int bidx = t * 4;
        int s4[4]; int tot = 0;
#pragma unroll
        for (int j = 0; j < 4; j++) { s4[j] = tot; tot += sm.cnt[bidx + j]; }
        int incl = tot;
#pragma unroll
        for (int off = 1; off < 32; off <<= 1) {
            int u = __shfl_up_sync(0xffffffffu, incl, off);
            if (lane >= off) incl += u;
        }
        if (lane == 31) sm.wa[w] = incl;
        __syncthreads();
        if (t < 8) {
            int u = sm.wa[t];
#pragma unroll
            for (int off = 1; off < 8; off <<= 1) {
                int x2 = __shfl_up_sync(0x000000ffu, u, off);
                if (t >= off) u += x2;
            }
            sm.wa[t] = u;
        }
        __syncthreads();
        int excl = ((w > 0) ? sm.wa[w - 1] : 0) + incl - tot;
#pragma unroll
        for (int j = 0; j < 4; j++) {
            int idx = bidx + j;
            if (idx < NPCELL) { int sv = excl + s4[j]; sm.cstart[idx] = sv; sm.cur[idx] = sv; }
        }
        if (bidx <= NPCELL && NPCELL < bidx + 4) sm.cstart[NPCELL] = excl + s4[NPCELL - bidx];
        // note: NPCELL=1000 -> handled by thread with bidx=1000 (t=250): s4[0] offset
    }
    __syncthreads();

    // ---- scatter points into block-private sorted table ----
#pragma unroll
    for (int k = 0; k < PPT; k++) {
        int cell = rc[k];
        if (cell >= 0) {
            int pos = atomicAdd(&sm.cur[cell], 1);
            sm.pts[pos] = make_float4(rx[k], ry[k], rz[k], 0.0f);
        }
    }
    __syncthreads();

    // ---- query: this thread's voxel against its 2x2x2 cell neighborhood ----
    const float ux = 2.0f * cx, uy = 2.0f * cy, uz = 2.0f * cz;
    const int ix0 = (int)floorf(4.0f * cx + 4.5f);   // in [0,8]
    const int iy0 = (int)floorf(4.0f * cy + 4.5f);
    const int iz0 = (int)floorf(4.0f * cz + 4.5f);

    float m0 = 1e30f, m1 = 1e30f;
#pragma unroll
    for (int a = 0; a < 2; a++) {
#pragma unroll
        for (int b = 0; b < 2; b++) {
            int cb = ((ix0 + a) * NPGRID + (iy0 + b)) * NPGRID + iz0;
            int s = sm.cstart[cb];
            int e = sm.cstart[cb + 2];               // z-cells iz0, iz0+1 contiguous
            int k = s;
            for (; k + 2 <= e; k += 2) {
                float4 p0 = sm.pts[k];
                float4 p1 = sm.pts[k + 1];
                float dx0 = ux - p0.x, dy0 = uy - p0.y, dz0 = uz - p0.z;
                float dx1 = ux - p1.x, dy1 = uy - p1.y, dz1 = uz - p1.z;
                m0 = fminf(m0, fmaf(dx0, dx0, fmaf(dy0, dy0, dz0 * dz0)));
                m1 = fminf(m1, fmaf(dx1, dx1, fmaf(dy1, dy1, dz1 * dz1)));
            }
            if (k < e) {
                float4 p = sm.pts[k];
                float dx = ux - p.x, dy = uy - p.y, dz = uz - p.z;
                m0 = fminf(m0, fmaf(dx, dx, fmaf(dy, dy, dz * dz)));
            }
        }
    }
    float m = fminf(m0, m1);

    float d = sqrtf(fmaxf(m, 0.0f));
    d = fminf(d, 0.25f);
    float o = fmaxf(1.0f - 4.0f * d, 0.0f);

    float aps = o, as1 = fo * o, as2 = mk * o, ams = mk;

    const unsigned full = 0xffffffffu;
#pragma unroll
    for (int off = 16; off > 0; off >>= 1) {
        aps += __shfl_down_sync(full, aps, off);
        as1 += __shfl_down_sync(full, as1, off);
        as2 += __shfl_down_sync(full, as2, off);
        ams += __shfl_down_sync(full, ams, off);
    }
    if (lane == 0) { sm.red[0][w] = aps; sm.red[1][w] = as1; sm.red[2][w] = as2; sm.red[3][w] = ams; }
    __syncthreads();
    if (t == 0) {
        float tps = 0.f, ts1 = 0.f, ts2 = 0.f, tms = 0.f;
#pragma unroll
        for (int i = 0; i < TPB / 32; i++) {
            tps += sm.red[0][i]; ts1 += sm.red[1][i];
            ts2 += sm.red[2][i]; tms += sm.red[3][i];
        }
        g_part[blockIdx.x] = make_float4(tps, ts1, ts2, tms);
        __threadfence();
        unsigned r = atomicAdd(&g_done, 1u);
        sm.amLast = (r == GRID - 1) ? 1u : 0u;
    }
    __syncthreads();

    // ---- last-finished block folds all partials into the scalar output ----
    if (sm.amLast) {
        float4 p = __ldcg(&g_part[t]);               // t in [0, 256) == GRID
#pragma unroll
        for (int off = 16; off > 0; off >>= 1) {
            p.x += __shfl_down_sync(full, p.x, off);
            p.y += __shfl_down_sync(full, p.y, off);
            p.z += __shfl_down_sync(full, p.z, off);
            p.w += __shfl_down_sync(full, p.w, off);
        }
        if (lane == 0) { sm.red[0][w] = p.x; sm.red[1][w] = p.y; sm.red[2][w] = p.z; sm.red[3][w] = p.w; }
        __syncthreads();
        if (t == 0) {
            double ps = 0.0, s1 = 0.0, s2 = 0.0, ms = 0.0;
#pragma unroll
            for (int i = 0; i < TPB / 32; i++) {
                ps += (double)sm.red[0][i]; s1 += (double)sm.red[1][i];
                s2 += (double)sm.red[2][i]; ms += (double)sm.red[3][i];
            }
            double t1 = (ps > 0.0) ? s1 / ps : 0.0;
            double t2 = (ms > 0.0) ? s2 / ms : 0.0;
            out[0] = (float)(t1 - t2);
            g_done = 0;                               // reset for next graph replay
        }
    }
}

extern "C" void kernel_launch(void* const* d_in, const int* in_sizes, int n_in,
                              void* d_out, int out_size) {
    const float* quat    = (const float*)d_in[0];
    const float* tran    = (const float*)d_in[1];
    const float* model   = (const float*)d_in[2];
    const float* view    = (const float*)d_in[3];
    const float* centers = (const float*)d_in[4];
    const float* freev   = (const float*)d_in[5];
    const float* occo    = (const float*)d_in[6];
    const float* masks   = (const float*)d_in[7];
    (void)in_sizes; (void)n_in; (void)out_size;

    icc_kernel<<<GRID, TPB>>>(quat, tran, model, view, centers,
                              freev, occo, masks, (float*)d_out);
}